// round 11
// baseline (speedup 1.0000x reference)
#include <cuda_runtime.h>
#include <cuda_bf16.h>
#include <math.h>

// MovingNormalizationLayer: 1-D moving-window (w=100) normalization along the
// last axis of [1,1,128,256,1024] fp32. Zero-padded window, denominator = 100
// everywhere -> clamped prefix-sum differences.
//
// R10: conflict-free ALIGNED prefix writes.
//  Thread t writes the 16B-aligned entry group 48+4t..51+4t as one STS.128
//  per array, deriving the two leading entries from excl minus the previous
//  thread's last two x values (shfl_up; warp boundaries via a staging buffer).
//  Reads keep the proven aligned layout (bytes 16t and 16t+400).

#define ROW_LEN 1024
#define WIN 100
#define HALF_L 50
#define THREADS 256
#define PAD_N (HALF_L + ROW_LEN + HALF_L + 4)   // 1128
#define FLT_MAX_C 3.4028234663852886e38f

__device__ __forceinline__ float fixup(float r) {
    r = (r != r) ? 0.0f : r;                       // nan -> 0
    return fminf(fmaxf(r, -FLT_MAX_C), FLT_MAX_C); // +/-inf -> +/-FLT_MAX
}

__device__ __forceinline__ float norm1(float xv, float slo, float shi,
                                       float qlo, float qhi) {
    const float sum  = shi - slo;
    const float sum2 = qhi - qlo;
    const float mean = sum * (1.0f / (float)WIN);
    const float var  = fmaf(sum2, (1.0f / (float)WIN), -mean * mean);
    return fixup((xv - mean) * rsqrtf(var));
}

__global__ __launch_bounds__(THREADS, 8)
void moving_norm_kernel(const float* __restrict__ x, float* __restrict__ out) {
    __shared__ __align__(16) float P [PAD_N];   // Ppad[j] = P[j-50] (j>=50)
    __shared__ __align__(16) float P2[PAD_N];
    __shared__ __align__(16) float2 ws[THREADS / 32];   // (warp sum, warp sum2)
    __shared__ __align__(8)  float2 xb[THREADS / 32];   // lane31's (v.z, v.w)

    const int t    = threadIdx.x;
    const int lane = t & 31;
    const int wid  = t >> 5;
    const int row_off = (int)(blockIdx.x << 10);

    // ---- coalesced float4 load of this thread's 4 contiguous elements ----
    const float4 v = reinterpret_cast<const float4*>(x + row_off)[t];

    const float xx = v.x * v.x, yy = v.y * v.y, zz = v.z * v.z, ww = v.w * v.w;
    const float s  = v.x + v.y + v.z + v.w;
    const float s2 = xx + yy + zz + ww;

    // left pad: entries 0..47 zero -> 12 threads x STS.128 per array
    if (t < 12) {
        reinterpret_cast<float4*>(P )[t] = make_float4(0.f, 0.f, 0.f, 0.f);
        reinterpret_cast<float4*>(P2)[t] = make_float4(0.f, 0.f, 0.f, 0.f);
    }

    // ---- warp inclusive scan (pair) ----
    float inc = s, inc2 = s2;
    #pragma unroll
    for (int off = 1; off < 32; off <<= 1) {
        const float a = __shfl_up_sync(0xffffffffu, inc,  off);
        const float b = __shfl_up_sync(0xffffffffu, inc2, off);
        if (lane >= off) { inc += a; inc2 += b; }
    }
    if (lane == 31) {
        ws[wid] = make_float2(inc, inc2);
        xb[wid] = make_float2(v.z, v.w);
    }
    __syncthreads();

    // warp partials via 4 broadcast LDS.128
    const float4 wa = reinterpret_cast<const float4*>(ws)[0];  // warps 0,1
    const float4 wb = reinterpret_cast<const float4*>(ws)[1];  // warps 2,3
    const float4 wc = reinterpret_cast<const float4*>(ws)[2];  // warps 4,5
    const float4 wd = reinterpret_cast<const float4*>(ws)[3];  // warps 6,7

    float woff = 0.f, woff2 = 0.f;
    if (wid > 0) { woff += wa.x; woff2 += wa.y; }
    if (wid > 1) { woff += wa.z; woff2 += wa.w; }
    if (wid > 2) { woff += wb.x; woff2 += wb.y; }
    if (wid > 3) { woff += wb.z; woff2 += wb.w; }
    if (wid > 4) { woff += wc.x; woff2 += wc.y; }
    if (wid > 5) { woff += wc.z; woff2 += wc.w; }
    if (wid > 6) { woff += wd.x; woff2 += wd.y; }

    const float excl  = woff  + inc  - s;    // P[4t]
    const float excl2 = woff2 + inc2 - s2;

    // previous thread's last two x values (x[4t-2], x[4t-1])
    float pz = __shfl_up_sync(0xffffffffu, v.z, 1);
    float pw = __shfl_up_sync(0xffffffffu, v.w, 1);
    if (lane == 0) {
        if (wid == 0) { pz = 0.f; pw = 0.f; }
        else { const float2 b = xb[wid - 1]; pz = b.x; pw = b.y; }
    }

    // ---- aligned group write: entries 48+4t..51+4t (one STS.128 per array) ----
    {
        float4 gp, gq;
        gp.x = excl - pw - pz;             // P[4t-2] (entry 48+4t; t=0 -> pad 0)
        gp.y = excl - pw;                  // P[4t-1]
        gp.z = excl;                       // P[4t]
        gp.w = excl + v.x;                 // P[4t+1]
        gq.x = excl2 - pw * pw - pz * pz;
        gq.y = excl2 - pw * pw;
        gq.z = excl2;
        gq.w = excl2 + xx;
        reinterpret_cast<float4*>(P )[12 + t] = gp;   // byte 192+16t, aligned
        reinterpret_cast<float4*>(P2)[12 + t] = gq;
    }
    // tail entries 1072,1073 = P[1022], P[1023] (last thread only)
    if (t == THREADS - 1) {
        const float tot  = excl  + s;      // P[1024]
        const float tot2 = excl2 + s2;
        *reinterpret_cast<float2*>(&P [1072]) = make_float2(tot  - v.w - v.z, tot  - v.w);
        *reinterpret_cast<float2*>(&P2[1072]) = make_float2(tot2 - ww  - zz,  tot2 - ww);
    }
    // right pad: entries 1074..1123 hold row totals -> 25 threads x STS.64 each
    if (t < HALF_L / 2) {
        const float T  = wa.x + wa.z + wb.x + wb.z + wc.x + wc.z + wd.x + wd.z;
        const float T2 = wa.y + wa.w + wb.y + wb.w + wc.y + wc.w + wd.y + wd.w;
        reinterpret_cast<float2*>(&P [HALF_L + ROW_LEN])[t] = make_float2(T,  T);
        reinterpret_cast<float2*>(&P2[HALF_L + ROW_LEN])[t] = make_float2(T2, T2);
    }
    __syncthreads();

    // ---- compute: 4 aligned, conflict-free LDS.128 ----
    // out[i]: lo = Ppad[4t..4t+3] (byte 16t), hi = Ppad[4t+100..] (byte 16t+400)
    const float4 plo = *reinterpret_cast<const float4*>(&P [4 * t]);
    const float4 phi = *reinterpret_cast<const float4*>(&P [4 * t + 2 * HALF_L]);
    const float4 qlo = *reinterpret_cast<const float4*>(&P2[4 * t]);
    const float4 qhi = *reinterpret_cast<const float4*>(&P2[4 * t + 2 * HALF_L]);

    float4 o;
    o.x = norm1(v.x, plo.x, phi.x, qlo.x, qhi.x);
    o.y = norm1(v.y, plo.y, phi.y, qlo.y, qhi.y);
    o.z = norm1(v.z, plo.z, phi.z, qlo.z, qhi.z);
    o.w = norm1(v.w, plo.w, phi.w, qlo.w, qhi.w);
    reinterpret_cast<float4*>(out + row_off)[t] = o;
}

extern "C" void kernel_launch(void* const* d_in, const int* in_sizes, int n_in,
                              void* d_out, int out_size) {
    const float* x = (const float*)d_in[0];
    float* out = (float*)d_out;
    const int total = in_sizes[0];          // 33,554,432
    const int rows  = total / ROW_LEN;      // 32,768
    moving_norm_kernel<<<rows, THREADS>>>(x, out);
}

// round 13
// speedup vs baseline: 1.2539x; 1.2539x over previous
#include <cuda_runtime.h>
#include <cuda_bf16.h>
#include <math.h>

// MovingNormalizationLayer: 1-D moving-window (w=100) normalization along the
// last axis of [1,1,128,256,1024] fp32. Zero-padded window, denominator = 100
// everywhere -> clamped prefix-sum differences.
//
// R11/R12 = R10 (aligned STS.128 prefix writes) with the register cap relaxed:
//  __launch_bounds__(256, 6) -> 40 regs. R10 spilled under the 32-reg cap
//  (L2% tripled = LDL/STL traffic); occupancy 48 warps/SM is still ample.

#define ROW_LEN 1024
#define WIN 100
#define HALF_L 50
#define THREADS 256
#define PAD_N (HALF_L + ROW_LEN + HALF_L + 4)   // 1128
#define FLT_MAX_C 3.4028234663852886e38f

__device__ __forceinline__ float fixup(float r) {
    r = (r != r) ? 0.0f : r;                       // nan -> 0
    return fminf(fmaxf(r, -FLT_MAX_C), FLT_MAX_C); // +/-inf -> +/-FLT_MAX
}

__device__ __forceinline__ float norm1(float xv, float slo, float shi,
                                       float qlo, float qhi) {
    const float sum  = shi - slo;
    const float sum2 = qhi - qlo;
    const float mean = sum * (1.0f / (float)WIN);
    const float var  = fmaf(sum2, (1.0f / (float)WIN), -mean * mean);
    return fixup((xv - mean) * rsqrtf(var));
}

__global__ __launch_bounds__(THREADS, 6)
void moving_norm_kernel(const float* __restrict__ x, float* __restrict__ out) {
    __shared__ __align__(16) float P [PAD_N];   // Ppad[j] = P[j-50] (j>=50)
    __shared__ __align__(16) float P2[PAD_N];
    __shared__ __align__(16) float2 ws[THREADS / 32];   // (warp sum, warp sum2)
    __shared__ __align__(8)  float2 xb[THREADS / 32];   // lane31's (v.z, v.w)

    const int t    = threadIdx.x;
    const int lane = t & 31;
    const int wid  = t >> 5;
    const int row_off = (int)(blockIdx.x << 10);

    // ---- coalesced float4 load of this thread's 4 contiguous elements ----
    const float4 v = reinterpret_cast<const float4*>(x + row_off)[t];

    const float s  = v.x + v.y + v.z + v.w;
    const float s2 = fmaf(v.x, v.x, fmaf(v.y, v.y, fmaf(v.z, v.z, v.w * v.w)));

    // left pad: entries 0..47 zero -> 12 threads x STS.128 per array
    if (t < 12) {
        reinterpret_cast<float4*>(P )[t] = make_float4(0.f, 0.f, 0.f, 0.f);
        reinterpret_cast<float4*>(P2)[t] = make_float4(0.f, 0.f, 0.f, 0.f);
    }

    // ---- warp inclusive scan (pair) ----
    float inc = s, inc2 = s2;
    #pragma unroll
    for (int off = 1; off < 32; off <<= 1) {
        const float a = __shfl_up_sync(0xffffffffu, inc,  off);
        const float b = __shfl_up_sync(0xffffffffu, inc2, off);
        if (lane >= off) { inc += a; inc2 += b; }
    }
    if (lane == 31) {
        ws[wid] = make_float2(inc, inc2);
        xb[wid] = make_float2(v.z, v.w);
    }
    __syncthreads();

    // warp partials via 4 broadcast LDS.128
    const float4 wa = reinterpret_cast<const float4*>(ws)[0];  // warps 0,1
    const float4 wb = reinterpret_cast<const float4*>(ws)[1];  // warps 2,3
    const float4 wc = reinterpret_cast<const float4*>(ws)[2];  // warps 4,5
    const float4 wd = reinterpret_cast<const float4*>(ws)[3];  // warps 6,7

    float woff = 0.f, woff2 = 0.f;
    if (wid > 0) { woff += wa.x; woff2 += wa.y; }
    if (wid > 1) { woff += wa.z; woff2 += wa.w; }
    if (wid > 2) { woff += wb.x; woff2 += wb.y; }
    if (wid > 3) { woff += wb.z; woff2 += wb.w; }
    if (wid > 4) { woff += wc.x; woff2 += wc.y; }
    if (wid > 5) { woff += wc.z; woff2 += wc.w; }
    if (wid > 6) { woff += wd.x; woff2 += wd.y; }

    const float excl  = woff  + inc  - s;    // P[4t]
    const float excl2 = woff2 + inc2 - s2;

    // previous thread's last two x values (x[4t-2], x[4t-1])
    const float sz = __shfl_up_sync(0xffffffffu, v.z, 1);
    const float sw = __shfl_up_sync(0xffffffffu, v.w, 1);
    const float2 bprev = xb[(wid == 0) ? 0 : (wid - 1)];
    const bool use_sh = (lane != 0);
    const float pz = use_sh ? sz : ((wid == 0) ? 0.f : bprev.x);
    const float pw = use_sh ? sw : ((wid == 0) ? 0.f : bprev.y);

    // ---- aligned group write: entries 48+4t..51+4t (one STS.128 per array) ----
    {
        const float pw2 = pw * pw;
        float4 gp, gq;
        gp.y = excl - pw;                  // P[4t-1]
        gp.x = gp.y - pz;                  // P[4t-2] (entry 48+4t; t=0 -> pad 0)
        gp.z = excl;                       // P[4t]
        gp.w = excl + v.x;                 // P[4t+1]
        gq.y = excl2 - pw2;
        gq.x = gq.y - pz * pz;
        gq.z = excl2;
        gq.w = fmaf(v.x, v.x, excl2);
        reinterpret_cast<float4*>(P )[12 + t] = gp;   // byte 192+16t, aligned
        reinterpret_cast<float4*>(P2)[12 + t] = gq;
    }
    // tail entries 1072,1073 = P[1022], P[1023] (last thread only)
    if (t == THREADS - 1) {
        const float tot  = excl  + s;      // P[1024]
        const float tot2 = excl2 + s2;
        *reinterpret_cast<float2*>(&P [1072]) = make_float2(tot  - v.w - v.z, tot  - v.w);
        *reinterpret_cast<float2*>(&P2[1072]) =
            make_float2(tot2 - v.w * v.w - v.z * v.z, tot2 - v.w * v.w);
    }
    // right pad: entries 1074..1123 hold row totals -> 25 threads x STS.64 each
    if (t < HALF_L / 2) {
        const float T  = wa.x + wa.z + wb.x + wb.z + wc.x + wc.z + wd.x + wd.z;
        const float T2 = wa.y + wa.w + wb.y + wb.w + wc.y + wc.w + wd.y + wd.w;
        reinterpret_cast<float2*>(&P [HALF_L + ROW_LEN])[t] = make_float2(T,  T);
        reinterpret_cast<float2*>(&P2[HALF_L + ROW_LEN])[t] = make_float2(T2, T2);
    }
    __syncthreads();

    // ---- compute: 4 aligned, conflict-free LDS.128 ----
    // out[i]: lo = Ppad[4t..4t+3] (byte 16t), hi = Ppad[4t+100..] (byte 16t+400)
    const float4 plo = *reinterpret_cast<const float4*>(&P [4 * t]);
    const float4 phi = *reinterpret_cast<const float4*>(&P [4 * t + 2 * HALF_L]);
    const float4 qlo = *reinterpret_cast<const float4*>(&P2[4 * t]);
    const float4 qhi = *reinterpret_cast<const float4*>(&P2[4 * t + 2 * HALF_L]);

    float4 o;
    o.x = norm1(v.x, plo.x, phi.x, qlo.x, qhi.x);
    o.y = norm1(v.y, plo.y, phi.y, qlo.y, qhi.y);
    o.z = norm1(v.z, plo.z, phi.z, qlo.z, qhi.z);
    o.w = norm1(v.w, plo.w, phi.w, qlo.w, qhi.w);
    reinterpret_cast<float4*>(out + row_off)[t] = o;
}

extern "C" void kernel_launch(void* const* d_in, const int* in_sizes, int n_in,
                              void* d_out, int out_size) {
    const float* x = (const float*)d_in[0];
    float* out = (float*)d_out;
    const int total = in_sizes[0];          // 33,554,432
    const int rows  = total / ROW_LEN;      // 32,768
    moving_norm_kernel<<<rows, THREADS>>>(x, out);
}

// round 15
// speedup vs baseline: 1.3283x; 1.0593x over previous
#include <cuda_runtime.h>
#include <cuda_bf16.h>
#include <math.h>

// MovingNormalizationLayer: 1-D moving-window (w=100) normalization along the
// last axis of [1,1,128,256,1024] fp32. Zero-padded window, denominator = 100
// everywhere -> clamped prefix-sum differences.
//
// R13/R14: register-cheap aligned prefix writes.
//  Thread t writes entries 52+4t..55+4t (= P[4t+2..4t+5]) as one STS.128 per
//  array; the only foreign value needed is the NEXT thread's v.x (one
//  shfl_down; warp boundary via staged lane-0 v.x). t=255 uses nx=0, whose
//  entry is exactly the right-pad total. Reads keep bytes 16t / 16t+400.

#define ROW_LEN 1024
#define WIN 100
#define HALF_L 50
#define THREADS 256
#define PAD_N (HALF_L + ROW_LEN + HALF_L + 4)   // 1128
#define FLT_MAX_C 3.4028234663852886e38f

__device__ __forceinline__ float fixup(float r) {
    r = (r != r) ? 0.0f : r;                       // nan -> 0
    return fminf(fmaxf(r, -FLT_MAX_C), FLT_MAX_C); // +/-inf -> +/-FLT_MAX
}

__device__ __forceinline__ float norm1(float xv, float slo, float shi,
                                       float qlo, float qhi) {
    const float sum  = shi - slo;
    const float sum2 = qhi - qlo;
    const float mean = sum * (1.0f / (float)WIN);
    const float var  = fmaf(sum2, (1.0f / (float)WIN), -mean * mean);
    return fixup((xv - mean) * rsqrtf(var));
}

__global__ __launch_bounds__(THREADS, 7)
void moving_norm_kernel(const float* __restrict__ x, float* __restrict__ out) {
    __shared__ __align__(16) float P [PAD_N];   // Ppad[50+i] = P[i]
    __shared__ __align__(16) float P2[PAD_N];
    __shared__ __align__(16) float2 ws[THREADS / 32];   // (warp sum, warp sum2)
    __shared__ float xb[THREADS / 32];                  // lane0's v.x per warp

    const int t    = threadIdx.x;
    const int lane = t & 31;
    const int wid  = t >> 5;
    const int row_off = (int)(blockIdx.x << 10);

    // ---- coalesced float4 load of this thread's 4 contiguous elements ----
    const float4 v = reinterpret_cast<const float4*>(x + row_off)[t];

    const float s  = v.x + v.y + v.z + v.w;
    const float s2 = fmaf(v.x, v.x, fmaf(v.y, v.y, fmaf(v.z, v.z, v.w * v.w)));

    // ---- warp inclusive scan (pair) ----
    float inc = s, inc2 = s2;
    #pragma unroll
    for (int off = 1; off < 32; off <<= 1) {
        const float a = __shfl_up_sync(0xffffffffu, inc,  off);
        const float b = __shfl_up_sync(0xffffffffu, inc2, off);
        if (lane >= off) { inc += a; inc2 += b; }
    }
    if (lane == 31) ws[wid] = make_float2(inc, inc2);
    if (lane == 0)  xb[wid] = v.x;
    __syncthreads();

    // warp partials via 4 broadcast LDS.128
    const float4 wa = reinterpret_cast<const float4*>(ws)[0];  // warps 0,1
    const float4 wb = reinterpret_cast<const float4*>(ws)[1];  // warps 2,3
    const float4 wc = reinterpret_cast<const float4*>(ws)[2];  // warps 4,5
    const float4 wd = reinterpret_cast<const float4*>(ws)[3];  // warps 6,7

    float woff = 0.f, woff2 = 0.f;
    if (wid > 0) { woff += wa.x; woff2 += wa.y; }
    if (wid > 1) { woff += wa.z; woff2 += wa.w; }
    if (wid > 2) { woff += wb.x; woff2 += wb.y; }
    if (wid > 3) { woff += wb.z; woff2 += wb.w; }
    if (wid > 4) { woff += wc.x; woff2 += wc.y; }
    if (wid > 5) { woff += wc.z; woff2 += wc.w; }
    if (wid > 6) { woff += wd.x; woff2 += wd.y; }

    const float excl  = woff  + inc  - s;    // P[4t]
    const float excl2 = woff2 + inc2 - s2;

    // next thread's v.x  (x[4t+4]); t=255 -> 0 (its entry 1075 is the pad total)
    const float nxs = __shfl_down_sync(0xffffffffu, v.x, 1);
    const float nx  = (lane != 31) ? nxs : ((wid < 7) ? xb[wid + 1] : 0.f);

    // ---- aligned group write: entries 52+4t..55+4t (one STS.128 per array) ----
    {
        float4 gp, gq;
        gp.x = excl + v.x + v.y;           // P[4t+2]
        gp.y = gp.x + v.z;                 // P[4t+3]
        gp.z = excl + s;                   // P[4t+4]
        gp.w = gp.z + nx;                  // P[4t+5]
        gq.x = excl2 + fmaf(v.x, v.x, v.y * v.y);
        gq.y = fmaf(v.z, v.z, gq.x);
        gq.z = excl2 + s2;
        gq.w = fmaf(nx, nx, gq.z);
        reinterpret_cast<float4*>(P )[13 + t] = gp;   // byte 208+16t, aligned
        reinterpret_cast<float4*>(P2)[13 + t] = gq;
    }
    // left pad: entries 0..51 (P[-50..1]); entry 51 = P[1] = x[0] via xb[0]
    if (t < 13) {
        const float x0 = xb[0];
        const float4 z = (t == 12) ? make_float4(0.f, 0.f, 0.f, x0)
                                   : make_float4(0.f, 0.f, 0.f, 0.f);
        const float4 z2 = (t == 12) ? make_float4(0.f, 0.f, 0.f, x0 * x0)
                                    : make_float4(0.f, 0.f, 0.f, 0.f);
        reinterpret_cast<float4*>(P )[t] = z;
        reinterpret_cast<float4*>(P2)[t] = z2;
    }
    // right pad: entries 1076..1123 -> 12 threads x STS.128 of the row totals
    if (t < 12) {
        const float T  = wa.x + wa.z + wb.x + wb.z + wc.x + wc.z + wd.x + wd.z;
        const float T2 = wa.y + wa.w + wb.y + wb.w + wc.y + wc.w + wd.y + wd.w;
        reinterpret_cast<float4*>(P )[269 + t] = make_float4(T,  T,  T,  T);
        reinterpret_cast<float4*>(P2)[269 + t] = make_float4(T2, T2, T2, T2);
    }
    __syncthreads();

    // ---- compute: 4 aligned, conflict-free LDS.128 ----
    // out[i]: lo = Ppad[4t..4t+3] (byte 16t), hi = Ppad[4t+100..] (byte 16t+400)
    const float4 plo = *reinterpret_cast<const float4*>(&P [4 * t]);
    const float4 phi = *reinterpret_cast<const float4*>(&P [4 * t + 2 * HALF_L]);
    const float4 qlo = *reinterpret_cast<const float4*>(&P2[4 * t]);
    const float4 qhi = *reinterpret_cast<const float4*>(&P2[4 * t + 2 * HALF_L]);

    float4 o;
    o.x = norm1(v.x, plo.x, phi.x, qlo.x, qhi.x);
    o.y = norm1(v.y, plo.y, phi.y, qlo.y, qhi.y);
    o.z = norm1(v.z, plo.z, phi.z, qlo.z, qhi.z);
    o.w = norm1(v.w, plo.w, phi.w, qlo.w, qhi.w);
    reinterpret_cast<float4*>(out + row_off)[t] = o;
}

extern "C" void kernel_launch(void* const* d_in, const int* in_sizes, int n_in,
                              void* d_out, int out_size) {
    const float* x = (const float*)d_in[0];
    float* out = (float*)d_out;
    const int total = in_sizes[0];          // 33,554,432
    const int rows  = total / ROW_LEN;      // 32,768
    moving_norm_kernel<<<rows, THREADS>>>(x, out);
}